// round 16
// baseline (speedup 1.0000x reference)
#include <cuda_runtime.h>
#include <cuda_fp16.h>
#include <cstdint>
#include <math.h>

#define NE 32
#define TOPK 8
#define HD 2048
#define ID 1024
#define NT 4096
#define TE (NT*TOPK)
#define MAXT 288
#define PTE (MAXT*128)      // padded position space (128-aligned expert groups)

#define KGX 132             // Xg kgroups: 128 X | 2 Zg | 2 Zu   (16 k each)
#define KGH 68              // Gh kgroups: 64 h | 2 Zd | 2 zero-pad

__device__ int g_cnt[NE], g_off[NE], g_cur[NE];
__device__ int g_tok[PTE], g_adp[PTE], g_pos[TE];
__device__ int g_te[MAXT], g_tm[MAXT], g_nt;
__device__ __half g_Xg[(size_t)PTE*KGX*16];            // fragment units
__device__ __half g_Gh[(size_t)PTE*KGH*16];            // kg 66,67 stay zero (never written)
__device__ __half g_O [(size_t)PTE*HD];                // down output, fp16
__device__ __half g_Wgu[(size_t)NE*128*KGX*256];       // fused gate|up image
__device__ __half g_Wd [(size_t)NE*128*KGH*256];       // kg 66,67 stay zero
__device__ __half g_Azt[(size_t)NE*4*128*256];
__device__ __half g_Adt[(size_t)NE*2*64*256];

__device__ __forceinline__ uint32_t smem_u32(const void* p) {
    uint32_t a;
    asm("{ .reg .u64 t; cvta.to.shared.u64 t, %1; cvt.u32.u64 %0, t; }" : "=r"(a) : "l"(p));
    return a;
}
__device__ __forceinline__ void cpa16(uint32_t dst, const void* src) {
    asm volatile("cp.async.cg.shared.global [%0], [%1], 16;" :: "r"(dst), "l"(src) : "memory");
}
__device__ __forceinline__ void cpa_commit() { asm volatile("cp.async.commit_group;" ::: "memory"); }
__device__ __forceinline__ void cpa_wait1()  { asm volatile("cp.async.wait_group 1;" ::: "memory"); }
__device__ __forceinline__ void mma16(float* c, const uint32_t* a, const uint32_t* b) {
    asm volatile(
        "mma.sync.aligned.m16n8k16.row.col.f32.f16.f16.f32 "
        "{%0,%1,%2,%3}, {%4,%5,%6,%7}, {%8,%9}, {%0,%1,%2,%3};\n"
        : "+f"(c[0]), "+f"(c[1]), "+f"(c[2]), "+f"(c[3])
        : "r"(a[0]), "r"(a[1]), "r"(a[2]), "r"(a[3]), "r"(b[0]), "r"(b[1]));
}
__device__ __forceinline__ __half2 h2f(float x, float y) {
    return __halves2half2(__float2half_rn(x), __float2half_rn(y));
}

// ---------------- routing (parallel): count -> scan(+reset) -> scatter ----------------
// g_cnt starts zeroed (module load); scan_kernel resets it after use so every
// graph replay sees zeroed counters -> deterministic.
__global__ void count_kernel(const int* __restrict__ sel) {
    __shared__ int c[NE];
    int tid = threadIdx.x;
    if (tid < NE) c[tid] = 0;
    __syncthreads();
    int stride = gridDim.x * blockDim.x;
    for (int i = blockIdx.x * blockDim.x + tid; i < TE; i += stride)
        atomicAdd(&c[sel[i]], 1);
    // zero padded-position arrays in parallel (no conflict with counting)
    for (int p = blockIdx.x * blockDim.x + tid; p < PTE; p += stride) {
        g_tok[p] = 0; g_adp[p] = 0;
    }
    __syncthreads();
    if (tid < NE && c[tid]) atomicAdd(&g_cnt[tid], c[tid]);
}

__global__ void scan_kernel() {
    if (threadIdx.x == 0) {
        int acc = 0, idx = 0;
        for (int e = 0; e < NE; e++) {
            int c = g_cnt[e];
            g_cnt[e] = 0;               // reset for next graph replay
            g_off[e] = acc; g_cur[e] = acc;
            int tl = (c + 127) >> 7;
            for (int i = 0; i < tl; i++) { g_te[idx] = e; g_tm[idx] = i; idx++; }
            acc += tl << 7;             // 128-aligned
        }
        g_nt = idx;
    }
}

__global__ void scatter_kernel(const int* __restrict__ sel, const int* __restrict__ adp) {
    int i = blockIdx.x * blockDim.x + threadIdx.x;
    if (i >= TE) return;
    int e = sel[i];
    int pos = atomicAdd(&g_cur[e], 1);
    int t = i >> 3;
    g_tok[pos] = t; g_adp[pos] = adp[t]; g_pos[i] = pos;
}

// ---------------- X pre-pass: gather + half + fragment units ----------------
__global__ void xconv(const float* __restrict__ hidden) {
    int P = blockIdx.x;
    if (P >= g_nt * 8) return;
    __shared__ int tk[16];
    int tid = threadIdx.x;
    if (tid < 16) tk[tid] = g_tok[P * 16 + tid];
    __syncthreads();
    #pragma unroll
    for (int i = 0; i < 16; i++) {
        int id = tid + (i << 8);               // 4096 units: kg 0..127, lane 0..31
        int kg = id >> 5, lane = id & 31;
        int r0 = lane >> 2;
        int kl = (kg << 4) + ((lane & 3) << 1);
        const float* s0 = hidden + (size_t)tk[r0] * HD;
        const float* s1 = hidden + (size_t)tk[r0 + 8] * HD;
        float2 a0 = *(const float2*)(s0 + kl);
        float2 a1 = *(const float2*)(s1 + kl);
        float2 b0 = *(const float2*)(s0 + kl + 8);
        float2 b1 = *(const float2*)(s1 + kl + 8);
        __half2 o[4] = { h2f(a0.x, a0.y), h2f(a1.x, a1.y), h2f(b0.x, b0.y), h2f(b1.x, b1.y) };
        *(uint4*)(g_Xg + (((size_t)P * KGX + kg) * 32 + lane) * 8) = *(uint4*)o;
    }
}

// ---------------- fused gate|up weight pre-pass ----------------
__global__ void wconv_gu(const float* __restrict__ Wg, const float* __restrict__ Wu,
                         const float* __restrict__ Bg, const float* __restrict__ Bu)
{
    __shared__ float sg[32][68], su[32][68];
    int e = blockIdx.z, ky = blockIdx.y, x = blockIdx.x;   // x: 64 real cols
    int tid = threadIdx.x;
    int rc0 = x << 6;
    #pragma unroll
    for (int i = 0; i < 2; i++) {
        int u = tid + (i << 8);
        int kk = u >> 4, c4 = (u & 15) << 2;
        float4 vg = make_float4(0,0,0,0), vu = vg;
        if (ky < 64) {
            vg = *(const float4*)(Wg + ((size_t)e * HD + (ky << 5) + kk) * ID + rc0 + c4);
            vu = *(const float4*)(Wu + ((size_t)e * HD + (ky << 5) + kk) * ID + rc0 + c4);
        } else if (ky == 64) {
            vg = *(const float4*)(Bg + (((size_t)(kk >> 4) * NE + e) * 16 + (kk & 15)) * ID + rc0 + c4);
        } else {
            vu = *(const float4*)(Bu + (((size_t)(kk >> 4) * NE + e) * 16 + (kk & 15)) * ID + rc0 + c4);
        }
        sg[kk][c4]=vg.x; sg[kk][c4+1]=vg.y; sg[kk][c4+2]=vg.z; sg[kk][c4+3]=vg.w;
        su[kk][c4]=vu.x; su[kk][c4+1]=vu.y; su[kk][c4+2]=vu.z; su[kk][c4+3]=vu.w;
    }
    __syncthreads();
    #pragma unroll
    for (int i = 0; i < 2; i++) {
        int u = tid + (i << 8);
        int ngl = u >> 6, kg = (u >> 5) & 1, lane = u & 31;
        int gc = (ngl << 3) + (lane >> 2);
        int kl = (kg << 4) + ((lane & 3) << 1);
        __half h[8];
        h[0]=__float2half_rn(sg[kl][gc]);   h[1]=__float2half_rn(sg[kl+1][gc]);
        h[2]=__float2half_rn(sg[kl+8][gc]); h[3]=__float2half_rn(sg[kl+9][gc]);
        h[4]=__float2half_rn(su[kl][gc]);   h[5]=__float2half_rn(su[kl+1][gc]);
        h[6]=__float2half_rn(su[kl+8][gc]); h[7]=__float2half_rn(su[kl+9][gc]);
        *(uint4*)(g_Wgu + ((((size_t)e*128 + (x<<3) + ngl) * KGX + (ky<<1) + kg) * 32 + lane) * 8) = *(uint4*)h;
    }
}

// ---------------- down weight pre-pass ----------------
__global__ void wconv_d(const float* __restrict__ Wd, const float* __restrict__ Bd) {
    __shared__ float s[32][132];
    int e = blockIdx.z, ky = blockIdx.y, x = blockIdx.x;
    int tid = threadIdx.x;
    int n0 = x << 7;
    #pragma unroll
    for (int i = 0; i < 4; i++) {
        int u = tid + (i << 8);
        int kk = u >> 5, c4 = (u & 31) << 2;
        float4 v;
        if (ky < 32) v = *(const float4*)(Wd + ((size_t)e * ID + (ky << 5) + kk) * HD + n0 + c4);
        else         v = *(const float4*)(Bd + (((size_t)(kk >> 4) * NE + e) * 16 + (kk & 15)) * HD + n0 + c4);
        s[kk][c4]=v.x; s[kk][c4+1]=v.y; s[kk][c4+2]=v.z; s[kk][c4+3]=v.w;
    }
    __syncthreads();
    #pragma unroll
    for (int i = 0; i < 2; i++) {
        int u = tid + (i << 8);
        int ngl = u >> 6, kg = (u >> 5) & 1, lane = u & 31;
        int c = (ngl << 4) + (lane >> 2);
        int kl = (kg << 4) + ((lane & 3) << 1);
        __half h[8];
        h[0]=__float2half_rn(s[kl][c]);     h[1]=__float2half_rn(s[kl+1][c]);
        h[2]=__float2half_rn(s[kl+8][c]);   h[3]=__float2half_rn(s[kl+9][c]);
        h[4]=__float2half_rn(s[kl][c+8]);   h[5]=__float2half_rn(s[kl+1][c+8]);
        h[6]=__float2half_rn(s[kl+8][c+8]); h[7]=__float2half_rn(s[kl+9][c+8]);
        *(uint4*)(g_Wd + ((((size_t)e*128 + (x<<3) + ngl) * KGH + (ky<<1) + kg) * 32 + lane) * 8) = *(uint4*)h;
    }
}

// ---------------- loraA pre-pass (fragment units) ----------------
__global__ void aconv(const float* __restrict__ Ag, const float* __restrict__ Au,
                      const float* __restrict__ Ad)
{
    int e = blockIdx.x, which = blockIdx.y, tid = threadIdx.x;
    int K = (which == 2) ? ID : HD;
    int KG = K >> 4;
    const float* A = (which == 0) ? Ag : (which == 1) ? Au : Ad;
    int units = 2 * KG * 32;
    for (int u = tid; u < units; u += 256) {
        int ngl = u / (KG * 32);
        int rem = u - ngl * KG * 32;
        int kg = rem >> 5, lane = rem & 31;
        int n0 = lane >> 2;
        int k = (kg << 4) + ((lane & 3) << 1);
        int a = ngl;
        const float* b0 = A + (((size_t)a * NE + e) * K + k) * 16;
        __half h[8];
        h[0]=__float2half_rn(b0[n0]);            h[1]=__float2half_rn(b0[16 + n0]);
        h[2]=__float2half_rn(b0[8*16 + n0]);     h[3]=__float2half_rn(b0[9*16 + n0]);
        h[4]=__float2half_rn(b0[n0+8]);          h[5]=__float2half_rn(b0[16 + n0+8]);
        h[6]=__float2half_rn(b0[8*16 + n0+8]);   h[7]=__float2half_rn(b0[9*16 + n0+8]);
        __half* dst = (which == 2)
            ? g_Adt + ((((size_t)e*2 + ngl) * 64 + kg) * 32 + lane) * 8
            : g_Azt + ((((size_t)e*4 + (which << 1) + ngl) * 128 + kg) * 32 + lane) * 8;
        *(uint4*)dst = *(uint4*)h;
    }
}

// ---------------- unified fp16 grouped GEMM, 64-k double chunks ----------------
// EPI 0: half natural store (down)  1: fused gate|up -> h units in Gh
// EPI 2: masked Zgu -> Xg kgrps 128+  3: masked Zd -> Gh kgrps 64+
template<int N_, int EPI>
__global__ __launch_bounds__(256, 2)
void mm(const __half* __restrict__ X, int KGXp,
        const __half* __restrict__ Wt, int KGW, int NGT, int KT,
        void* __restrict__ OutV)
{
    if ((int)blockIdx.y >= g_nt) return;
    const int e   = g_te[blockIdx.y];
    const int m0  = g_tm[blockIdx.y] << 7;
    const int posbase = g_off[e] + m0;
    const int Pbase = posbase >> 4;
    const int n0  = blockIdx.x * N_;
    const int tid = threadIdx.x, lane = tid & 31, wid = tid >> 5;
    constexpr int MW = 256 / N_;
    constexpr int MF = 8 / MW;
    constexpr int XSB = 16384;                // X stage bytes (128 rows x 64 k)
    constexpr int WSB = N_ * 128;             // B stage bytes
    constexpr int STGB = XSB + WSB;
    const int rg0 = (wid % MW) * MF;          // row-group base (16-row units)
    const int cb4 = (wid / MW) * 2;           // ngroup base (2 ngroups per warp)

    extern __shared__ __half sm[];
    const uint32_t smb = smem_u32(sm);
    const size_t WB = (size_t)e * NGT + (n0 >> 4);

    auto issue = [&](int kc, int buf) {
        #pragma unroll
        for (int i = 0; i < 4; i++) {
            int u = tid + (i << 8);
            cpa16(smb + buf * STGB + u * 16,
                  X + (((size_t)(Pbase + (u >> 7)) * KGXp + (kc << 2) + ((u >> 5) & 3)) * 32 + (u & 31)) * 8);
        }
        #pragma unroll
        for (int i = 0; i < (N_ >> 5); i++) {
            int v = tid + (i << 8);
            cpa16(smb + buf * STGB + XSB + v * 16,
                  Wt + (((WB + (v >> 7)) * KGW + (kc << 2) + ((v >> 5) & 3)) * 32 + (v & 31)) * 8);
        }
    };

    float acc[MF][4][4];
    #pragma unroll
    for (int i = 0; i < MF; i++)
        #pragma unroll
        for (int j = 0; j < 4; j++) { acc[i][j][0]=0.f; acc[i][j][1]=0.f; acc[i][j][2]=0.f; acc[i][j][3]=0.f; }

    issue(0, 0); cpa_commit();
    issue(1, 1); cpa_commit();

    for (int kc = 0; kc < KT; kc++) {
        cpa_wait1();
        __syncthreads();
        if (kc + 2 < KT) issue(kc + 2, (kc + 2) % 3);
        cpa_commit();
        const __half* xs = sm + (kc % 3) * (STGB / 2);
        const __half* ws = xs + XSB / 2;
        #pragma unroll
        for (int ks = 0; ks < 4; ks++) {
            uint32_t A[MF][4];
            #pragma unroll
            for (int mf = 0; mf < MF; mf++) {
                uint4 q = *(const uint4*)(xs + ((((rg0 + mf) << 2) + ks) * 32 + lane) * 8);
                A[mf][0] = q.x; A[mf][1] = q.y; A[mf][2] = q.z; A[mf][3] = q.w;
            }
            uint32_t B[4][2];
            #pragma unroll
            for (int pi = 0; pi < 2; pi++) {
                uint4 q = *(const uint4*)(ws + ((((cb4 + pi) << 2) + ks) * 32 + lane) * 8);
                B[2*pi][0] = q.x; B[2*pi][1] = q.y;
                B[2*pi+1][0] = q.z; B[2*pi+1][1] = q.w;
            }
            #pragma unroll
            for (int mf = 0; mf < MF; mf++)
                #pragma unroll
                for (int nf = 0; nf < 4; nf++)
                    mma16(acc[mf][nf], A[mf], B[nf]);
        }
    }

    // ---------------- epilogue ----------------
    const int outlane = ((lane >> 2) << 2) + (lane & 3);
    #pragma unroll
    for (int mf = 0; mf < MF; mf++) {
        int rl0 = ((rg0 + mf) << 4) + (lane >> 2);
        int p0 = posbase + rl0;
        if (EPI == 0) {
            __half* Out = (__half*)OutV;
            #pragma unroll
            for (int nf = 0; nf < 4; nf++) {
                int cl = (cb4 << 4) + (nf << 3) + ((lane & 3) << 1);
                *(__half2*)(Out + (size_t)p0 * HD + n0 + cl) = h2f(acc[mf][nf][0], acc[mf][nf][1]);
                *(__half2*)(Out + (size_t)(p0 + 8) * HD + n0 + cl) = h2f(acc[mf][nf][2], acc[mf][nf][3]);
            }
        } else if (EPI == 1) {
            __half* Out = (__half*)OutV;
            int kq = ((n0 >> 1) + (cb4 << 3)) >> 4;
            float h[8];
            #pragma unroll
            for (int pi = 0; pi < 2; pi++) {
                #pragma unroll
                for (int q = 0; q < 4; q++) {
                    float g = acc[mf][2*pi][q], u = acc[mf][2*pi+1][q];
                    h[pi*4 + q] = u * g / (1.f + __expf(-g));
                }
            }
            __half2 o[4] = { h2f(h[0],h[1]), h2f(h[2],h[3]), h2f(h[4],h[5]), h2f(h[6],h[7]) };
            size_t P = (size_t)(Pbase + rg0 + mf);
            *(uint4*)(Out + ((P * KGH + kq) * 32 + outlane) * 8) = *(uint4*)o;
        } else {
            __half* Out = (__half*)OutV;
            int a0 = g_adp[p0], a1 = g_adp[p0 + 8];
            size_t P = (size_t)(Pbase + rg0 + mf);
            #pragma unroll
            for (int P2 = 0; P2 < 2; P2++) {
                int slot = (cb4 + P2) & 1;
                int kq = (EPI == 2 ? 128 : 64) + cb4 + P2;
                float v0 = (slot == a0) ? 1.f : 0.f;
                float v1 = (slot == a1) ? 1.f : 0.f;
                __half2 o[4] = {
                    h2f(acc[mf][2*P2][0]*v0,   acc[mf][2*P2][1]*v0),
                    h2f(acc[mf][2*P2][2]*v1,   acc[mf][2*P2][3]*v1),
                    h2f(acc[mf][2*P2+1][0]*v0, acc[mf][2*P2+1][1]*v0),
                    h2f(acc[mf][2*P2+1][2]*v1, acc[mf][2*P2+1][3]*v1) };
                int KGO = (EPI == 2) ? KGX : KGH;
                *(uint4*)(Out + ((P * KGO + kq) * 32 + outlane) * 8) = *(uint4*)o;
            }
        }
    }
}

// ---------------- combine (half O) ----------------
__global__ void combine_kernel(const float* __restrict__ rw, float* __restrict__ out) {
    int t = blockIdx.x;
    __shared__ int s_pos[TOPK];
    __shared__ float s_w[TOPK];
    if (threadIdx.x < TOPK) {
        s_pos[threadIdx.x] = g_pos[t*TOPK + threadIdx.x];
        s_w[threadIdx.x]   = __ldg(rw + t*TOPK + threadIdx.x);
    }
    __syncthreads();
    int h = threadIdx.x * 8;                  // 256 threads x 8 = 2048 = HD
    float acc[8] = {0.f,0.f,0.f,0.f,0.f,0.f,0.f,0.f};
    #pragma unroll
    for (int k = 0; k < TOPK; k++) {
        const __half2* v = (const __half2*)(g_O + (size_t)s_pos[k]*HD + h);
        float w = s_w[k];
        #pragma unroll
        for (int q = 0; q < 4; q++) {
            float2 f = __half22float2(__ldg(v + q));
            acc[2*q]   += w * f.x;
            acc[2*q+1] += w * f.y;
        }
    }
    float4* o = (float4*)(out + (size_t)t*HD + h);
    o[0] = make_float4(acc[0], acc[1], acc[2], acc[3]);
    o[1] = make_float4(acc[4], acc[5], acc[6], acc[7]);
}

#define SM128 (3*(16384 + 128*128))
#define SM64  (3*(16384 +  64*128))
#define SM32  (3*(16384 +  32*128))

extern "C" void kernel_launch(void* const* d_in, const int* in_sizes, int n_in,
                              void* d_out, int out_size) {
    const float* hidden = (const float*)d_in[0];
    const int*   sel    = (const int*)  d_in[1];
    const float* rw     = (const float*)d_in[2];
    const int*   adp    = (const int*)  d_in[3];
    const float* Wg     = (const float*)d_in[4];
    const float* Ag     = (const float*)d_in[5];
    const float* Bg     = (const float*)d_in[6];
    const float* Wu     = (const float*)d_in[7];
    const float* Au     = (const float*)d_in[8];
    const float* Bu     = (const float*)d_in[9];
    const float* Wd     = (const float*)d_in[10];
    const float* Ad     = (const float*)d_in[11];
    const float* Bd     = (const float*)d_in[12];
    float* out = (float*)d_out;

    static bool init = false;
    static cudaStream_t s1;
    static cudaEvent_t evRoot, evA, evGU, evD;
    if (!init) {
        cudaFuncSetAttribute(mm<128,0>, cudaFuncAttributeMaxDynamicSharedMemorySize, SM128);
        cudaFuncSetAttribute(mm<128,1>, cudaFuncAttributeMaxDynamicSharedMemorySize, SM128);
        cudaFuncSetAttribute(mm<64,2>,  cudaFuncAttributeMaxDynamicSharedMemorySize, SM64);
        cudaFuncSetAttribute(mm<32,3>,  cudaFuncAttributeMaxDynamicSharedMemorySize, SM32);
        cudaStreamCreateWithFlags(&s1, cudaStreamNonBlocking);
        cudaEventCreateWithFlags(&evRoot, cudaEventDisableTiming);
        cudaEventCreateWithFlags(&evA,    cudaEventDisableTiming);
        cudaEventCreateWithFlags(&evGU,   cudaEventDisableTiming);
        cudaEventCreateWithFlags(&evD,    cudaEventDisableTiming);
        init = true;
    }

    __half *Xg, *Gh, *O, *Wgu, *Wdp, *Azt, *Adt;
    cudaGetSymbolAddress((void**)&Xg,  g_Xg);
    cudaGetSymbolAddress((void**)&Gh,  g_Gh);
    cudaGetSymbolAddress((void**)&O,   g_O);
    cudaGetSymbolAddress((void**)&Wgu, g_Wgu);
    cudaGetSymbolAddress((void**)&Wdp, g_Wd);
    cudaGetSymbolAddress((void**)&Azt, g_Azt);
    cudaGetSymbolAddress((void**)&Adt, g_Adt);

    // ---- fork: weight/lora pre-passes on side stream ----
    cudaEventRecord(evRoot, 0);
    cudaStreamWaitEvent(s1, evRoot, 0);
    aconv<<<dim3(NE, 3), 256, 0, s1>>>(Ag, Au, Ad);
    cudaEventRecord(evA, s1);
    wconv_gu<<<dim3(16, 66, NE), 256, 0, s1>>>(Wg, Wu, Bg, Bu);
    cudaEventRecord(evGU, s1);
    wconv_d<<<dim3(16, 33, NE), 256, 0, s1>>>(Wd, Bd);
    cudaEventRecord(evD, s1);

    // ---- main stream: critical path ----
    count_kernel<<<296, 256>>>(sel);
    scan_kernel<<<1, 32>>>();
    scatter_kernel<<<128, 256>>>(sel, adp);
    xconv<<<MAXT*8, 256>>>(hidden);

    cudaStreamWaitEvent(0, evA, 0);    // need Azt/Adt
    // Z(gate|up) -> Xg kgrps 128..131 (adapter-masked); 32 double-chunks
    mm<64,2><<<dim3(1, MAXT), 256, SM64>>>(Xg, KGX, Azt, 128, 4, 32, Xg);

    cudaStreamWaitEvent(0, evGU, 0);   // need Wgu
    // fused gate+up -> Gh (h = silu(g)*u); 33 double-chunks
    mm<128,1><<<dim3(16, MAXT), 256, SM128>>>(Xg, KGX, Wgu, KGX, 128, 33, Gh);

    // Z(down) -> Gh kgrps 64..65; 16 double-chunks (Adt ready via evA)
    mm<32,3><<<dim3(1, MAXT), 256, SM32>>>(Gh, KGH, Adt, 64, 2, 16, Gh);

    cudaStreamWaitEvent(0, evD, 0);    // need Wd (joins side stream)
    // down -> O (half natural); 17 double-chunks (kg 66,67 zeros both sides)
    mm<128,0><<<dim3(16, MAXT), 256, SM128>>>(Gh, KGH, Wdp, KGH, 128, 17, O);

    combine_kernel<<<NT, 256>>>(rw, out);
}

// round 17
// speedup vs baseline: 1.0108x; 1.0108x over previous
#include <cuda_runtime.h>
#include <cuda_fp16.h>
#include <cstdint>
#include <math.h>

#define NE 32
#define TOPK 8
#define HD 2048
#define ID 1024
#define NT 4096
#define TE (NT*TOPK)
#define MAXT 288
#define PTE (MAXT*128)      // padded position space (128-aligned expert groups)

#define KGX 132             // Xg kgroups: 128 X | 2 Zg | 2 Zu   (16 k each)
#define KGH 68              // Gh kgroups: 64 h | 2 Zd | 2 zero-pad

__device__ int g_cnt[NE], g_off[NE], g_cur[NE];
__device__ int g_tok[PTE], g_adp[PTE], g_pos[TE];
__device__ int g_te[MAXT], g_tm[MAXT], g_nt;
__device__ __half g_Xg[(size_t)PTE*KGX*16];            // fragment units
__device__ __half g_Gh[(size_t)PTE*KGH*16];            // kg 66,67 stay zero (never written)
__device__ __half g_O [(size_t)PTE*HD];                // down output, fp16
__device__ __half g_Wgu[(size_t)NE*128*KGX*256];       // fused gate|up image
__device__ __half g_Wd [(size_t)NE*128*KGH*256];       // kg 66,67 stay zero
__device__ __half g_Azt[(size_t)NE*4*128*256];
__device__ __half g_Adt[(size_t)NE*2*64*256];

__device__ __forceinline__ uint32_t smem_u32(const void* p) {
    uint32_t a;
    asm("{ .reg .u64 t; cvta.to.shared.u64 t, %1; cvt.u32.u64 %0, t; }" : "=r"(a) : "l"(p));
    return a;
}
__device__ __forceinline__ void cpa16(uint32_t dst, const void* src) {
    asm volatile("cp.async.cg.shared.global [%0], [%1], 16;" :: "r"(dst), "l"(src) : "memory");
}
__device__ __forceinline__ void cpa_commit() { asm volatile("cp.async.commit_group;" ::: "memory"); }
__device__ __forceinline__ void cpa_wait1()  { asm volatile("cp.async.wait_group 1;" ::: "memory"); }
__device__ __forceinline__ void mma16(float* c, const uint32_t* a, const uint32_t* b) {
    asm volatile(
        "mma.sync.aligned.m16n8k16.row.col.f32.f16.f16.f32 "
        "{%0,%1,%2,%3}, {%4,%5,%6,%7}, {%8,%9}, {%0,%1,%2,%3};\n"
        : "+f"(c[0]), "+f"(c[1]), "+f"(c[2]), "+f"(c[3])
        : "r"(a[0]), "r"(a[1]), "r"(a[2]), "r"(a[3]), "r"(b[0]), "r"(b[1]));
}
__device__ __forceinline__ __half2 h2f(float x, float y) {
    return __halves2half2(__float2half_rn(x), __float2half_rn(y));
}

// ---------------- routing (parallel, R15 champion config) ----------------
__global__ void zcnt_kernel() {
    if (threadIdx.x < NE) g_cnt[threadIdx.x] = 0;
}

__global__ void count_kernel(const int* __restrict__ sel) {
    __shared__ int c[NE];
    int tid = threadIdx.x;
    if (tid < NE) c[tid] = 0;
    __syncthreads();
    int stride = gridDim.x * blockDim.x;
    for (int i = blockIdx.x * blockDim.x + tid; i < TE; i += stride)
        atomicAdd(&c[sel[i]], 1);
    for (int p = blockIdx.x * blockDim.x + tid; p < PTE; p += stride) {
        g_tok[p] = 0; g_adp[p] = 0;
    }
    __syncthreads();
    if (tid < NE && c[tid]) atomicAdd(&g_cnt[tid], c[tid]);
}

__global__ void scan_kernel() {
    if (threadIdx.x == 0) {
        int acc = 0, idx = 0;
        for (int e = 0; e < NE; e++) {
            int c = g_cnt[e];
            g_off[e] = acc; g_cur[e] = acc;
            int tl = (c + 127) >> 7;
            for (int i = 0; i < tl; i++) { g_te[idx] = e; g_tm[idx] = i; idx++; }
            acc += tl << 7;             // 128-aligned
        }
        g_nt = idx;
    }
}

__global__ void scatter_kernel(const int* __restrict__ sel, const int* __restrict__ adp) {
    int i = blockIdx.x * blockDim.x + threadIdx.x;
    if (i >= TE) return;
    int e = sel[i];
    int pos = atomicAdd(&g_cur[e], 1);
    int t = i >> 3;
    g_tok[pos] = t; g_adp[pos] = adp[t]; g_pos[i] = pos;
}

// ---------------- X pre-pass: gather + half + fragment units ----------------
__global__ void xconv(const float* __restrict__ hidden) {
    int P = blockIdx.x;
    if (P >= g_nt * 8) return;
    __shared__ int tk[16];
    int tid = threadIdx.x;
    if (tid < 16) tk[tid] = g_tok[P * 16 + tid];
    __syncthreads();
    #pragma unroll
    for (int i = 0; i < 16; i++) {
        int id = tid + (i << 8);               // 4096 units: kg 0..127, lane 0..31
        int kg = id >> 5, lane = id & 31;
        int r0 = lane >> 2;
        int kl = (kg << 4) + ((lane & 3) << 1);
        const float* s0 = hidden + (size_t)tk[r0] * HD;
        const float* s1 = hidden + (size_t)tk[r0 + 8] * HD;
        float2 a0 = *(const float2*)(s0 + kl);
        float2 a1 = *(const float2*)(s1 + kl);
        float2 b0 = *(const float2*)(s0 + kl + 8);
        float2 b1 = *(const float2*)(s1 + kl + 8);
        __half2 o[4] = { h2f(a0.x, a0.y), h2f(a1.x, a1.y), h2f(b0.x, b0.y), h2f(b1.x, b1.y) };
        *(uint4*)(g_Xg + (((size_t)P * KGX + kg) * 32 + lane) * 8) = *(uint4*)o;
    }
}

// ---------------- fused gate|up weight pre-pass ----------------
__global__ void wconv_gu(const float* __restrict__ Wg, const float* __restrict__ Wu,
                         const float* __restrict__ Bg, const float* __restrict__ Bu)
{
    __shared__ float sg[32][68], su[32][68];
    int e = blockIdx.z, ky = blockIdx.y, x = blockIdx.x;   // x: 64 real cols
    int tid = threadIdx.x;
    int rc0 = x << 6;
    #pragma unroll
    for (int i = 0; i < 2; i++) {
        int u = tid + (i << 8);
        int kk = u >> 4, c4 = (u & 15) << 2;
        float4 vg = make_float4(0,0,0,0), vu = vg;
        if (ky < 64) {
            vg = *(const float4*)(Wg + ((size_t)e * HD + (ky << 5) + kk) * ID + rc0 + c4);
            vu = *(const float4*)(Wu + ((size_t)e * HD + (ky << 5) + kk) * ID + rc0 + c4);
        } else if (ky == 64) {
            vg = *(const float4*)(Bg + (((size_t)(kk >> 4) * NE + e) * 16 + (kk & 15)) * ID + rc0 + c4);
        } else {
            vu = *(const float4*)(Bu + (((size_t)(kk >> 4) * NE + e) * 16 + (kk & 15)) * ID + rc0 + c4);
        }
        sg[kk][c4]=vg.x; sg[kk][c4+1]=vg.y; sg[kk][c4+2]=vg.z; sg[kk][c4+3]=vg.w;
        su[kk][c4]=vu.x; su[kk][c4+1]=vu.y; su[kk][c4+2]=vu.z; su[kk][c4+3]=vu.w;
    }
    __syncthreads();
    #pragma unroll
    for (int i = 0; i < 2; i++) {
        int u = tid + (i << 8);
        int ngl = u >> 6, kg = (u >> 5) & 1, lane = u & 31;
        int gc = (ngl << 3) + (lane >> 2);
        int kl = (kg << 4) + ((lane & 3) << 1);
        __half h[8];
        h[0]=__float2half_rn(sg[kl][gc]);   h[1]=__float2half_rn(sg[kl+1][gc]);
        h[2]=__float2half_rn(sg[kl+8][gc]); h[3]=__float2half_rn(sg[kl+9][gc]);
        h[4]=__float2half_rn(su[kl][gc]);   h[5]=__float2half_rn(su[kl+1][gc]);
        h[6]=__float2half_rn(su[kl+8][gc]); h[7]=__float2half_rn(su[kl+9][gc]);
        *(uint4*)(g_Wgu + ((((size_t)e*128 + (x<<3) + ngl) * KGX + (ky<<1) + kg) * 32 + lane) * 8) = *(uint4*)h;
    }
}

// ---------------- down weight pre-pass ----------------
__global__ void wconv_d(const float* __restrict__ Wd, const float* __restrict__ Bd) {
    __shared__ float s[32][132];
    int e = blockIdx.z, ky = blockIdx.y, x = blockIdx.x;
    int tid = threadIdx.x;
    int n0 = x << 7;
    #pragma unroll
    for (int i = 0; i < 4; i++) {
        int u = tid + (i << 8);
        int kk = u >> 5, c4 = (u & 31) << 2;
        float4 v;
        if (ky < 32) v = *(const float4*)(Wd + ((size_t)e * ID + (ky << 5) + kk) * HD + n0 + c4);
        else         v = *(const float4*)(Bd + (((size_t)(kk >> 4) * NE + e) * 16 + (kk & 15)) * HD + n0 + c4);
        s[kk][c4]=v.x; s[kk][c4+1]=v.y; s[kk][c4+2]=v.z; s[kk][c4+3]=v.w;
    }
    __syncthreads();
    #pragma unroll
    for (int i = 0; i < 2; i++) {
        int u = tid + (i << 8);
        int ngl = u >> 6, kg = (u >> 5) & 1, lane = u & 31;
        int c = (ngl << 4) + (lane >> 2);
        int kl = (kg << 4) + ((lane & 3) << 1);
        __half h[8];
        h[0]=__float2half_rn(s[kl][c]);     h[1]=__float2half_rn(s[kl+1][c]);
        h[2]=__float2half_rn(s[kl+8][c]);   h[3]=__float2half_rn(s[kl+9][c]);
        h[4]=__float2half_rn(s[kl][c+8]);   h[5]=__float2half_rn(s[kl+1][c+8]);
        h[6]=__float2half_rn(s[kl+8][c+8]); h[7]=__float2half_rn(s[kl+9][c+8]);
        *(uint4*)(g_Wd + ((((size_t)e*128 + (x<<3) + ngl) * KGH + (ky<<1) + kg) * 32 + lane) * 8) = *(uint4*)h;
    }
}

// ---------------- loraA pre-pass (fragment units) ----------------
__global__ void aconv(const float* __restrict__ Ag, const float* __restrict__ Au,
                      const float* __restrict__ Ad)
{
    int e = blockIdx.x, which = blockIdx.y, tid = threadIdx.x;
    int K = (which == 2) ? ID : HD;
    int KG = K >> 4;
    const float* A = (which == 0) ? Ag : (which == 1) ? Au : Ad;
    int units = 2 * KG * 32;
    for (int u = tid; u < units; u += 256) {
        int ngl = u / (KG * 32);
        int rem = u - ngl * KG * 32;
        int kg = rem >> 5, lane = rem & 31;
        int n0 = lane >> 2;
        int k = (kg << 4) + ((lane & 3) << 1);
        int a = ngl;
        const float* b0 = A + (((size_t)a * NE + e) * K + k) * 16;
        __half h[8];
        h[0]=__float2half_rn(b0[n0]);            h[1]=__float2half_rn(b0[16 + n0]);
        h[2]=__float2half_rn(b0[8*16 + n0]);     h[3]=__float2half_rn(b0[9*16 + n0]);
        h[4]=__float2half_rn(b0[n0+8]);          h[5]=__float2half_rn(b0[16 + n0+8]);
        h[6]=__float2half_rn(b0[8*16 + n0+8]);   h[7]=__float2half_rn(b0[9*16 + n0+8]);
        __half* dst = (which == 2)
            ? g_Adt + ((((size_t)e*2 + ngl) * 64 + kg) * 32 + lane) * 8
            : g_Azt + ((((size_t)e*4 + (which << 1) + ngl) * 128 + kg) * 32 + lane) * 8;
        *(uint4*)dst = *(uint4*)h;
    }
}

// ---------------- unified fp16 grouped GEMM, 64-k double chunks ----------------
// EPI 0: half natural store (down)  1: fused gate|up -> h units in Gh
// EPI 2: masked Zgu -> Xg kgrps 128+  3: masked Zd -> Gh kgrps 64+
// nbase: column offset added to blockIdx.x*N_ (for split down halves)
template<int N_, int EPI>
__global__ __launch_bounds__(256, 2)
void mm(const __half* __restrict__ X, int KGXp,
        const __half* __restrict__ Wt, int KGW, int NGT, int KT,
        void* __restrict__ OutV, int nbase)
{
    if ((int)blockIdx.y >= g_nt) return;
    const int e   = g_te[blockIdx.y];
    const int m0  = g_tm[blockIdx.y] << 7;
    const int posbase = g_off[e] + m0;
    const int Pbase = posbase >> 4;
    const int n0  = blockIdx.x * N_ + nbase;
    const int tid = threadIdx.x, lane = tid & 31, wid = tid >> 5;
    constexpr int MW = 256 / N_;
    constexpr int MF = 8 / MW;
    constexpr int XSB = 16384;                // X stage bytes (128 rows x 64 k)
    constexpr int WSB = N_ * 128;             // B stage bytes
    constexpr int STGB = XSB + WSB;
    const int rg0 = (wid % MW) * MF;          // row-group base (16-row units)
    const int cb4 = (wid / MW) * 2;           // ngroup base (2 ngroups per warp)

    extern __shared__ __half sm[];
    const uint32_t smb = smem_u32(sm);
    const size_t WB = (size_t)e * NGT + (n0 >> 4);

    auto issue = [&](int kc, int buf) {
        #pragma unroll
        for (int i = 0; i < 4; i++) {
            int u = tid + (i << 8);
            cpa16(smb + buf * STGB + u * 16,
                  X + (((size_t)(Pbase + (u >> 7)) * KGXp + (kc << 2) + ((u >> 5) & 3)) * 32 + (u & 31)) * 8);
        }
        #pragma unroll
        for (int i = 0; i < (N_ >> 5); i++) {
            int v = tid + (i << 8);
            cpa16(smb + buf * STGB + XSB + v * 16,
                  Wt + (((WB + (v >> 7)) * KGW + (kc << 2) + ((v >> 5) & 3)) * 32 + (v & 31)) * 8);
        }
    };

    float acc[MF][4][4];
    #pragma unroll
    for (int i = 0; i < MF; i++)
        #pragma unroll
        for (int j = 0; j < 4; j++) { acc[i][j][0]=0.f; acc[i][j][1]=0.f; acc[i][j][2]=0.f; acc[i][j][3]=0.f; }

    issue(0, 0); cpa_commit();
    issue(1, 1); cpa_commit();

    for (int kc = 0; kc < KT; kc++) {
        cpa_wait1();
        __syncthreads();
        if (kc + 2 < KT) issue(kc + 2, (kc + 2) % 3);
        cpa_commit();
        const __half* xs = sm + (kc % 3) * (STGB / 2);
        const __half* ws = xs + XSB / 2;
        #pragma unroll
        for (int ks = 0; ks < 4; ks++) {
            uint32_t A[MF][4];
            #pragma unroll
            for (int mf = 0; mf < MF; mf++) {
                uint4 q = *(const uint4*)(xs + ((((rg0 + mf) << 2) + ks) * 32 + lane) * 8);
                A[mf][0] = q.x; A[mf][1] = q.y; A[mf][2] = q.z; A[mf][3] = q.w;
            }
            uint32_t B[4][2];
            #pragma unroll
            for (int pi = 0; pi < 2; pi++) {
                uint4 q = *(const uint4*)(ws + ((((cb4 + pi) << 2) + ks) * 32 + lane) * 8);
                B[2*pi][0] = q.x; B[2*pi][1] = q.y;
                B[2*pi+1][0] = q.z; B[2*pi+1][1] = q.w;
            }
            #pragma unroll
            for (int mf = 0; mf < MF; mf++)
                #pragma unroll
                for (int nf = 0; nf < 4; nf++)
                    mma16(acc[mf][nf], A[mf], B[nf]);
        }
    }

    // ---------------- epilogue ----------------
    const int outlane = ((lane >> 2) << 2) + (lane & 3);
    #pragma unroll
    for (int mf = 0; mf < MF; mf++) {
        int rl0 = ((rg0 + mf) << 4) + (lane >> 2);
        int p0 = posbase + rl0;
        if (EPI == 0) {
            __half* Out = (__half*)OutV;
            #pragma unroll
            for (int nf = 0; nf < 4; nf++) {
                int cl = (cb4 << 4) + (nf << 3) + ((lane & 3) << 1);
                *(__half2*)(Out + (size_t)p0 * HD + n0 + cl) = h2f(acc[mf][nf][0], acc[mf][nf][1]);
                *(__half2*)(Out + (size_t)(p0 + 8) * HD + n0 + cl) = h2f(acc[mf][nf][2], acc[mf][nf][3]);
            }
        } else if (EPI == 1) {
            __half* Out = (__half*)OutV;
            int kq = ((n0 >> 1) + (cb4 << 3)) >> 4;
            float h[8];
            #pragma unroll
            for (int pi = 0; pi < 2; pi++) {
                #pragma unroll
                for (int q = 0; q < 4; q++) {
                    float g = acc[mf][2*pi][q], u = acc[mf][2*pi+1][q];
                    h[pi*4 + q] = u * g / (1.f + __expf(-g));
                }
            }
            __half2 o[4] = { h2f(h[0],h[1]), h2f(h[2],h[3]), h2f(h[4],h[5]), h2f(h[6],h[7]) };
            size_t P = (size_t)(Pbase + rg0 + mf);
            *(uint4*)(Out + ((P * KGH + kq) * 32 + outlane) * 8) = *(uint4*)o;
        } else {
            __half* Out = (__half*)OutV;
            int a0 = g_adp[p0], a1 = g_adp[p0 + 8];
            size_t P = (size_t)(Pbase + rg0 + mf);
            #pragma unroll
            for (int P2 = 0; P2 < 2; P2++) {
                int slot = (cb4 + P2) & 1;
                int kq = (EPI == 2 ? 128 : 64) + cb4 + P2;
                float v0 = (slot == a0) ? 1.f : 0.f;
                float v1 = (slot == a1) ? 1.f : 0.f;
                __half2 o[4] = {
                    h2f(acc[mf][2*P2][0]*v0,   acc[mf][2*P2][1]*v0),
                    h2f(acc[mf][2*P2][2]*v1,   acc[mf][2*P2][3]*v1),
                    h2f(acc[mf][2*P2+1][0]*v0, acc[mf][2*P2+1][1]*v0),
                    h2f(acc[mf][2*P2+1][2]*v1, acc[mf][2*P2+1][3]*v1) };
                int KGO = (EPI == 2) ? KGX : KGH;
                *(uint4*)(Out + ((P * KGO + kq) * 32 + outlane) * 8) = *(uint4*)o;
            }
        }
    }
}

// ---------------- combine (half O), over column range [hb, hb+1024) ----------------
__global__ void combine_kernel(const float* __restrict__ rw, float* __restrict__ out, int hb) {
    int t = blockIdx.x;
    __shared__ int s_pos[TOPK];
    __shared__ float s_w[TOPK];
    if (threadIdx.x < TOPK) {
        s_pos[threadIdx.x] = g_pos[t*TOPK + threadIdx.x];
        s_w[threadIdx.x]   = rw[t*TOPK + threadIdx.x];
    }
    __syncthreads();
    int h = hb + threadIdx.x * 8;             // 128 threads x 8 = 1024 cols
    float acc[8] = {0.f,0.f,0.f,0.f,0.f,0.f,0.f,0.f};
    #pragma unroll
    for (int k = 0; k < TOPK; k++) {
        const __half2* v = (const __half2*)(g_O + (size_t)s_pos[k]*HD + h);
        float w = s_w[k];
        #pragma unroll
        for (int q = 0; q < 4; q++) {
            float2 f = __half22float2(v[q]);
            acc[2*q]   += w * f.x;
            acc[2*q+1] += w * f.y;
        }
    }
    float4* o = (float4*)(out + (size_t)t*HD + h);
    o[0] = make_float4(acc[0], acc[1], acc[2], acc[3]);
    o[1] = make_float4(acc[4], acc[5], acc[6], acc[7]);
}

#define SM128 (3*(16384 + 128*128))
#define SM64  (3*(16384 +  64*128))
#define SM32  (3*(16384 +  32*128))

extern "C" void kernel_launch(void* const* d_in, const int* in_sizes, int n_in,
                              void* d_out, int out_size) {
    const float* hidden = (const float*)d_in[0];
    const int*   sel    = (const int*)  d_in[1];
    const float* rw     = (const float*)d_in[2];
    const int*   adp    = (const int*)  d_in[3];
    const float* Wg     = (const float*)d_in[4];
    const float* Ag     = (const float*)d_in[5];
    const float* Bg     = (const float*)d_in[6];
    const float* Wu     = (const float*)d_in[7];
    const float* Au     = (const float*)d_in[8];
    const float* Bu     = (const float*)d_in[9];
    const float* Wd     = (const float*)d_in[10];
    const float* Ad     = (const float*)d_in[11];
    const float* Bd     = (const float*)d_in[12];
    float* out = (float*)d_out;

    static bool init = false;
    static cudaStream_t s1;
    static cudaEvent_t evRoot, evA, evGU, evD, evGh, evDhi;
    if (!init) {
        cudaFuncSetAttribute(mm<128,0>, cudaFuncAttributeMaxDynamicSharedMemorySize, SM128);
        cudaFuncSetAttribute(mm<128,1>, cudaFuncAttributeMaxDynamicSharedMemorySize, SM128);
        cudaFuncSetAttribute(mm<64,2>,  cudaFuncAttributeMaxDynamicSharedMemorySize, SM64);
        cudaFuncSetAttribute(mm<32,3>,  cudaFuncAttributeMaxDynamicSharedMemorySize, SM32);
        cudaStreamCreateWithFlags(&s1, cudaStreamNonBlocking);
        cudaEventCreateWithFlags(&evRoot, cudaEventDisableTiming);
        cudaEventCreateWithFlags(&evA,    cudaEventDisableTiming);
        cudaEventCreateWithFlags(&evGU,   cudaEventDisableTiming);
        cudaEventCreateWithFlags(&evD,    cudaEventDisableTiming);
        cudaEventCreateWithFlags(&evGh,   cudaEventDisableTiming);
        cudaEventCreateWithFlags(&evDhi,  cudaEventDisableTiming);
        init = true;
    }

    __half *Xg, *Gh, *O, *Wgu, *Wdp, *Azt, *Adt;
    cudaGetSymbolAddress((void**)&Xg,  g_Xg);
    cudaGetSymbolAddress((void**)&Gh,  g_Gh);
    cudaGetSymbolAddress((void**)&O,   g_O);
    cudaGetSymbolAddress((void**)&Wgu, g_Wgu);
    cudaGetSymbolAddress((void**)&Wdp, g_Wd);
    cudaGetSymbolAddress((void**)&Azt, g_Azt);
    cudaGetSymbolAddress((void**)&Adt, g_Adt);

    // ---- fork: weight/lora pre-passes on side stream ----
    cudaEventRecord(evRoot, 0);
    cudaStreamWaitEvent(s1, evRoot, 0);
    aconv<<<dim3(NE, 3), 256, 0, s1>>>(Ag, Au, Ad);
    cudaEventRecord(evA, s1);
    wconv_gu<<<dim3(16, 66, NE), 256, 0, s1>>>(Wg, Wu, Bg, Bu);
    cudaEventRecord(evGU, s1);
    wconv_d<<<dim3(16, 33, NE), 256, 0, s1>>>(Wd, Bd);
    cudaEventRecord(evD, s1);

    // ---- main stream: critical path ----
    zcnt_kernel<<<1, 32>>>();
    count_kernel<<<128, 256>>>(sel);
    scan_kernel<<<1, 32>>>();
    scatter_kernel<<<128, 256>>>(sel, adp);
    xconv<<<MAXT*8, 256>>>(hidden);

    cudaStreamWaitEvent(0, evA, 0);    // need Azt/Adt
    // Z(gate|up) -> Xg kgrps 128..131 (adapter-masked); 32 double-chunks
    mm<64,2><<<dim3(1, MAXT), 256, SM64>>>(Xg, KGX, Azt, 128, 4, 32, Xg, 0);

    cudaStreamWaitEvent(0, evGU, 0);   // need Wgu
    // fused gate+up -> Gh (h = silu(g)*u); 33 double-chunks
    mm<128,1><<<dim3(16, MAXT), 256, SM128>>>(Xg, KGX, Wgu, KGX, 128, 33, Gh, 0);

    // Z(down) -> Gh kgrps 64..65; 16 double-chunks (Adt ready via evA)
    mm<32,3><<<dim3(1, MAXT), 256, SM32>>>(Gh, KGH, Adt, 64, 2, 16, Gh, 0);
    cudaEventRecord(evGh, 0);          // Gh complete

    // ---- down split: lo on stream0, hi on s1 (s1 already did wconv_d) ----
    cudaStreamWaitEvent(0, evD, 0);    // stream0 needs Wd
    cudaStreamWaitEvent(s1, evGh, 0);  // s1 needs Gh
    mm<128,0><<<dim3(8, MAXT), 256, SM128>>>(Gh, KGH, Wdp, KGH, 128, 17, O, 0);
    mm<128,0><<<dim3(8, MAXT), 256, SM128, s1>>>(Gh, KGH, Wdp, KGH, 128, 17, O, 1024);
    cudaEventRecord(evDhi, s1);

    // combine lo overlaps down_hi tail; hi joins both streams
    combine_kernel<<<NT, 128>>>(rw, out, 0);
    cudaStreamWaitEvent(0, evDhi, 0);
    combine_kernel<<<NT, 128>>>(rw, out, 1024);
}